// round 15
// baseline (speedup 1.0000x reference)
#include <cuda_runtime.h>
#include <cuda_fp16.h>
#include <math.h>
#include <stdint.h>

#define BATCH   2
#define SEQ     1024
#define DMODEL  1024
#define NLAYER  4
#define VOCAB   32000
#define DSTATE  16
#define DCONV   4
#define DINNER  2048
#define DTRANK  64
#define TTOK    (BATCH*SEQ)
#define XDBL_W  96
#define XP_SPLIT 8
#define OP_SPLIT 2
#define SEG     8
#define SEGLEN  (SEQ/SEG)    // 128

// -------- fp32 scratch --------
__device__ float g_h   [TTOK*DMODEL];
__device__ float g_xz  [TTOK*2*DINNER];
__device__ float g_xct [DINNER*TTOK];            // conv out, TRANSPOSED [c][t]
__device__ float g_dtt [DINNER*TTOK];            // softplus(dt), TRANSPOSED [c][t]
__device__ float g_Bt  [DSTATE*TTOK];            // B, TRANSPOSED [s][t]
__device__ float g_Ct  [DSTATE*TTOK];            // C, TRANSPOSED [s][t]
__device__ float g_xpp [XP_SPLIT*TTOK*XDBL_W];
__device__ float g_opp [OP_SPLIT*TTOK*DMODEL];
__device__ float g_Pseg[BATCH*DINNER*DSTATE*SEG];
__device__ float g_Hseg[BATCH*DINNER*DSTATE*SEG];
// -------- fp16 activations --------
__device__ __half g_xn_f[TTOK*DMODEL];
__device__ __half g_xc_f[TTOK*DINNER];
__device__ __half g_xd_f[TTOK*XDBL_W];
__device__ __half g_y_f [TTOK*DINNER];
// -------- fp16 weights --------
__device__ __half g_win_f [NLAYER*2*DINNER*DMODEL];
__device__ __half g_wout_f[NLAYER*DMODEL*DINNER];
__device__ __half g_wxp_f [NLAYER*XDBL_W*DINNER];
__device__ __half g_wdt_f [NLAYER*DINNER*DTRANK];
__device__ __half g_wemb_f[VOCAB*DMODEL];

// ---------------- helpers ----------------
__device__ __forceinline__ void cp16(uint32_t dst, const void* src, int srcBytes) {
    asm volatile("cp.async.cg.shared.global [%0], [%1], 16, %2;"
                 :: "r"(dst), "l"(src), "r"(srcBytes));
}
__device__ __forceinline__ void cp_commit() { asm volatile("cp.async.commit_group;"); }
template<int N> __device__ __forceinline__ void cp_wait() {
    asm volatile("cp.async.wait_group %0;" :: "n"(N));
}
__device__ __forceinline__ void ldsm4(uint32_t* r, uint32_t addr) {
    asm volatile("ldmatrix.sync.aligned.m8n8.x4.shared.b16 {%0,%1,%2,%3}, [%4];"
                 : "=r"(r[0]), "=r"(r[1]), "=r"(r[2]), "=r"(r[3]) : "r"(addr));
}
__device__ __forceinline__ void mma16(float* d, const uint32_t* a, uint32_t b0, uint32_t b1) {
    asm volatile(
        "mma.sync.aligned.m16n8k16.row.col.f32.f16.f16.f32 "
        "{%0,%1,%2,%3}, {%4,%5,%6,%7}, {%8,%9}, {%0,%1,%2,%3};\n"
        : "+f"(d[0]), "+f"(d[1]), "+f"(d[2]), "+f"(d[3])
        : "r"(a[0]), "r"(a[1]), "r"(a[2]), "r"(a[3]), "r"(b0), "r"(b1));
}
__device__ __forceinline__ uint32_t pack2h(float a, float b) {
    __half2 p = __floats2half2_rn(a, b);
    return *(uint32_t*)&p;
}

// ---------------- elementwise kernels ----------------
__global__ void cvt_all_k(const float* __restrict__ s0, __half* __restrict__ d0, int n0,
                          const float* __restrict__ s1, __half* __restrict__ d1, int n1,
                          const float* __restrict__ s2, __half* __restrict__ d2, int n2,
                          const float* __restrict__ s3, __half* __restrict__ d3, int n3,
                          const float* __restrict__ s4, __half* __restrict__ d4, int n4)
{
    int i = blockIdx.x * blockDim.x + threadIdx.x;
    const float* s; __half* d; int j = i;
    if (i < n0)                       { s = s0; d = d0; }
    else if ((j -= n0) < n1)          { s = s1; d = d1; }
    else if ((j -= n1) < n2)          { s = s2; d = d2; }
    else if ((j -= n2) < n3)          { s = s3; d = d3; }
    else if ((j -= n3) < n4)          { s = s4; d = d4; }
    else return;
    float4 v = ((const float4*)s)[j];
    uint2 p;
    p.x = pack2h(v.x, v.y);
    p.y = pack2h(v.z, v.w);
    ((uint2*)d)[j] = p;
}

__global__ void embed_k(const int* __restrict__ tok, const float* __restrict__ emb,
                        float* __restrict__ out)
{
    int t = blockIdx.x;
    int row = tok[t];
    ((float4*)(out + (size_t)t * DMODEL))[threadIdx.x] =
        ((const float4*)(emb + (size_t)row * DMODEL))[threadIdx.x];
}

__global__ void rmsnorm_k(const float* __restrict__ x, const float* __restrict__ w,
                          __half* __restrict__ oh)
{
    int t = blockIdx.x;
    int tid = threadIdx.x;
    float4 v = ((const float4*)(x + (size_t)t * DMODEL))[tid];
    float ss = v.x*v.x + v.y*v.y + v.z*v.z + v.w*v.w;
    __shared__ float sbuf[8];
    #pragma unroll
    for (int o = 16; o; o >>= 1) ss += __shfl_xor_sync(0xffffffffu, ss, o);
    int warp = tid >> 5, lane = tid & 31;
    if (lane == 0) sbuf[warp] = ss;
    __syncthreads();
    if (warp == 0) {
        float s2 = (lane < 8) ? sbuf[lane] : 0.f;
        #pragma unroll
        for (int o = 4; o; o >>= 1) s2 += __shfl_xor_sync(0xffffffffu, s2, o);
        if (lane == 0) sbuf[0] = rsqrtf(s2 * (1.0f / DMODEL) + 1e-5f);
    }
    __syncthreads();
    float r = sbuf[0];
    float4 wv = ((const float4*)w)[tid];
    uint2 p;
    p.x = pack2h(v.x*r*wv.x, v.y*r*wv.y);
    p.y = pack2h(v.z*r*wv.z, v.w*r*wv.w);
    ((uint2*)(oh + (size_t)t * DMODEL))[tid] = p;
}

// fused: h += opp0 + opp1; xnf = rmsnorm(h, w) in fp16
__global__ void resid_norm_k(const float* __restrict__ parts, float* __restrict__ h,
                             const float* __restrict__ w, __half* __restrict__ oh)
{
    int t = blockIdx.x;
    int tid = threadIdx.x;
    size_t ro = (size_t)t * 256 + tid;
    float4 v = ((const float4*)h)[ro];
    float4 a = ((const float4*)parts)[ro];
    float4 b = ((const float4*)(parts + (size_t)TTOK * DMODEL))[ro];
    v.x += a.x + b.x; v.y += a.y + b.y;
    v.z += a.z + b.z; v.w += a.w + b.w;
    ((float4*)h)[ro] = v;

    float ss = v.x*v.x + v.y*v.y + v.z*v.z + v.w*v.w;
    __shared__ float sbuf[8];
    #pragma unroll
    for (int o = 16; o; o >>= 1) ss += __shfl_xor_sync(0xffffffffu, ss, o);
    int warp = tid >> 5, lane = tid & 31;
    if (lane == 0) sbuf[warp] = ss;
    __syncthreads();
    if (warp == 0) {
        float s2 = (lane < 8) ? sbuf[lane] : 0.f;
        #pragma unroll
        for (int o = 4; o; o >>= 1) s2 += __shfl_xor_sync(0xffffffffu, s2, o);
        if (lane == 0) sbuf[0] = rsqrtf(s2 * (1.0f / DMODEL) + 1e-5f);
    }
    __syncthreads();
    float r = sbuf[0];
    float4 wv = ((const float4*)w)[tid];
    uint2 p;
    p.x = pack2h(v.x*r*wv.x, v.y*r*wv.y);
    p.y = pack2h(v.z*r*wv.z, v.w*r*wv.w);
    ((uint2*)(oh + (size_t)t * DMODEL))[tid] = p;
}

// conv: 4 timesteps/thread; writes xcf fp16 [t][c] (GEMM) + xct fp32 [c][t] (scan)
__global__ void conv_silu_k(const float* __restrict__ xz, const float* __restrict__ cw,
                            const float* __restrict__ cb, float* __restrict__ xct,
                            __half* __restrict__ xch)
{
    int idx = blockIdx.x * blockDim.x + threadIdx.x;   // over (TTOK/4)*DINNER
    if (idx >= (TTOK/4) * DINNER) return;
    int c  = idx % DINNER;
    int t4 = idx / DINNER;
    int t0 = t4 * 4;
    int l0 = t0 % SEQ;

    float4 w4 = *(const float4*)(cw + c * 4);
    float bias = cb[c];
    const size_t str = 2 * DINNER;

    float v[7];
    #pragma unroll
    for (int j = 0; j < 7; j++) {
        int l = l0 + j - 3;
        v[j] = (l >= 0) ? xz[(size_t)(t0 + j - 3) * str + c] : 0.f;
    }
    float4 o4;
    float* ov = (float*)&o4;
    #pragma unroll
    for (int j = 0; j < 4; j++) {
        float acc = bias + w4.x * v[j] + w4.y * v[j+1] + w4.z * v[j+2] + w4.w * v[j+3];
        float s = 1.f / (1.f + expf(-acc));
        float o = acc * s;
        ov[j] = o;
        xch[(size_t)(t0 + j) * DINNER + c] = __float2half_rn(o);
    }
    *(float4*)(xct + (size_t)c * TTOK + t0) = o4;
}

// x_proj split-K reduce -> xdf fp16 [t][96] (for dt GEMM) + Bt/Ct fp32 transposed
__global__ void reduce_xp_k(const float* __restrict__ parts,
                            __half* __restrict__ xdf,
                            float* __restrict__ Bt, float* __restrict__ Ct)
{
    int i = blockIdx.x * blockDim.x + threadIdx.x;
    if (i >= TTOK * XDBL_W) return;
    float s = 0.f;
    #pragma unroll
    for (int p = 0; p < XP_SPLIT; p++)
        s += parts[(size_t)p * TTOK * XDBL_W + i];
    xdf[i] = __float2half_rn(s);
    int t = i / XDBL_W, col = i % XDBL_W;
    if (col >= DTRANK) {
        if (col < DTRANK + DSTATE)
            Bt[(size_t)(col - DTRANK) * TTOK + t] = s;
        else
            Ct[(size_t)(col - DTRANK - DSTATE) * TTOK + t] = s;
    }
}

// ---------------- segmented selective scan (transposed float4 loads) ----------
// grid: 2048 blocks = B(2) x cgrp(128) x seg(8), 256 thr = 16 chan x 16 state
__global__ __launch_bounds__(256)
void scan1_k(const float* __restrict__ Bt, const float* __restrict__ dtt,
             const float* __restrict__ xct, const float* __restrict__ A_log,
             float* __restrict__ Pseg, float* __restrict__ Hseg)
{
    int tid = threadIdx.x;
    int s = tid & 15;
    int bid = blockIdx.x;
    int seg  = bid & 7;
    int cgrp = (bid >> 3) & 127;
    int b    = bid >> 10;
    int c = (cgrp << 4) + (tid >> 4);

    float A = -expf(A_log[(size_t)c * DSTATE + s]);
    int t0 = b * SEQ + seg * SEGLEN;

    const float4* dp = (const float4*)(dtt + (size_t)c * TTOK + t0);
    const float4* xp = (const float4*)(xct + (size_t)c * TTOK + t0);
    const float4* Bp = (const float4*)(Bt  + (size_t)s * TTOK + t0);

    float P = 1.f, H = 0.f;
    #pragma unroll 2
    for (int q = 0; q < SEGLEN/4; q++) {
        float4 d = dp[q], x = xp[q], Bv = Bp[q];
        float dA;
        dA = __expf(d.x * A); H = dA * H + (d.x * x.x) * Bv.x; P *= dA;
        dA = __expf(d.y * A); H = dA * H + (d.y * x.y) * Bv.y; P *= dA;
        dA = __expf(d.z * A); H = dA * H + (d.z * x.z) * Bv.z; P *= dA;
        dA = __expf(d.w * A); H = dA * H + (d.w * x.w) * Bv.w; P *= dA;
    }
    int idx = ((((b * DINNER + c) << 4) + s) << 3) + seg;
    Pseg[idx] = P;
    Hseg[idx] = H;
}

__global__ __launch_bounds__(256)
void scan2_k(const float* __restrict__ Bt, const float* __restrict__ Ct,
             const float* __restrict__ dtt, const float* __restrict__ xct,
             const float* __restrict__ xz,
             const float* __restrict__ A_log, const float* __restrict__ Dsk,
             const float* __restrict__ Pseg,  const float* __restrict__ Hseg,
             __half* __restrict__ yh)
{
    int tid = threadIdx.x;
    int s = tid & 15;
    int bid = blockIdx.x;
    int seg  = bid & 7;
    int cgrp = (bid >> 3) & 127;
    int b    = bid >> 10;
    int c = (cgrp << 4) + (tid >> 4);

    float A = -expf(A_log[(size_t)c * DSTATE + s]);
    float dval = Dsk[c];
    bool lane0 = (s == 0);

    int base = (((b * DINNER + c) << 4) + s) << 3;
    float h = 0.f;
    for (int j = 0; j < seg; j++)
        h = Pseg[base + j] * h + Hseg[base + j];

    int t0 = b * SEQ + seg * SEGLEN;
    const float4* dp = (const float4*)(dtt + (size_t)c * TTOK + t0);
    const float4* xp = (const float4*)(xct + (size_t)c * TTOK + t0);
    const float4* Bp = (const float4*)(Bt  + (size_t)s * TTOK + t0);
    const float4* Cp = (const float4*)(Ct  + (size_t)s * TTOK + t0);

    #pragma unroll 2
    for (int q = 0; q < SEGLEN/4; q++) {
        float4 d = dp[q], x = xp[q], Bv = Bp[q], Cv = Cp[q];
        const float* dd = (const float*)&d;
        const float* xx = (const float*)&x;
        const float* bb = (const float*)&Bv;
        const float* cc = (const float*)&Cv;
        #pragma unroll
        for (int j = 0; j < 4; j++) {
            float dA = __expf(dd[j] * A);
            h = dA * h + (dd[j] * xx[j]) * bb[j];
            float p = h * cc[j];
            p += __shfl_xor_sync(0xffffffffu, p, 8);
            p += __shfl_xor_sync(0xffffffffu, p, 4);
            p += __shfl_xor_sync(0xffffffffu, p, 2);
            p += __shfl_xor_sync(0xffffffffu, p, 1);
            if (lane0) {
                int t = t0 + q*4 + j;
                float z = xz[(size_t)t * (2*DINNER) + DINNER + c];
                float sg = 1.f / (1.f + __expf(-z));
                yh[(size_t)t * DINNER + c] = __float2half_rn((p + dval * xx[j]) * (z * sg));
            }
        }
    }
}

// ----------------------------------------------------------
// FP16 HMMA GEMM (NT). EPI: 0=store 1=accum 2=softplus+bias+TRANSPOSED store
// ----------------------------------------------------------
#define KCH     64
#define ROWB    144

template<int EPI, int BM, int BN, int MB>
__global__ __launch_bounds__(256, MB)
void mma_gemm(const __half* __restrict__ A, int lda,
              const __half* __restrict__ W, int ldw,
              float* __restrict__ C, int ldc,
              const float* __restrict__ bias,
              int N, int K, int zstride)
{
    constexpr int WM    = BM / 64;
    constexpr int WNW   = 8 / WM;
    constexpr int WN    = BN / WNW;
    constexpr int NFR   = WN / 8;
    constexpr int NBL   = WN / 16;
    constexpr int TILEA = BM * ROWB;
    constexpr int TILEB = BN * ROWB;
    constexpr int STAGE = TILEA + TILEB;
    constexpr int NTASK = (BM + BN) * 8;

    extern __shared__ char smem[];
    uint32_t sb = (uint32_t)__cvta_generic_to_shared(smem);

    int tid = threadIdx.x, lane = tid & 31, warp = tid >> 5;
    int wm = warp % WM;
    int wn = warp / WM;
    int tileM = blockIdx.y * BM, tileN = blockIdx.x * BN;

    int z = blockIdx.z;
    A += (size_t)z * K;
    W += (size_t)z * K;
    C += (size_t)z * zstride;

    float acc[4][NFR][4];
    #pragma unroll
    for (int mi = 0; mi < 4; mi++)
        #pragma unroll
        for (int ni = 0; ni < NFR; ni++)
            #pragma unroll
            for (int e = 0; e < 4; e++) acc[mi][ni][e] = 0.f;

    const int iters = K / KCH;

    uint32_t laneAoff = (uint32_t)((wm*64 + (lane & 15)) * ROWB + ((lane >> 4) & 1) * 16);
    uint32_t laneBoff = (uint32_t)((wn*WN + (lane & 7) + ((lane >= 16) ? 8 : 0)) * ROWB
                                   + ((lane >> 3) & 1) * 16);

    auto load_chunk = [&](int s, int it) {
        int k0 = it * KCH;
        uint32_t sbase = sb + (uint32_t)(s * STAGE);
        #pragma unroll
        for (int i = 0; i < NTASK/256; i++) {
            int task = tid + i * 256;
            if (task < BM*8) {
                int r = task >> 3, c = task & 7;
                cp16(sbase + (uint32_t)(r * ROWB + c * 16),
                     A + (size_t)(tileM + r) * lda + k0 + c * 8, 16);
            } else {
                int t2 = task - BM*8;
                int r = t2 >> 3, c = t2 & 7;
                int wr = tileN + r;
                const __half* src = W + (size_t)(wr < N ? wr : 0) * ldw + k0 + c * 8;
                cp16(sbase + (uint32_t)(TILEA + r * ROWB + c * 16),
                     src, wr < N ? 16 : 0);
            }
        }
        cp_commit();
    };

    if (iters > 0) load_chunk(0, 0);
    if (iters > 1) load_chunk(1, 1);

    for (int it = 0; it < iters; it++) {
        if (iters - 1 - it >= 1) cp_wait<1>();
        else                     cp_wait<0>();
        __syncthreads();
        if (it + 2 < iters) load_chunk((it + 2) % 3, it + 2);

        int s = it % 3;
        uint32_t stA = sb + s*STAGE + laneAoff;
        uint32_t stB = sb + s*STAGE + TILEA + laneBoff;

        #pragma unroll
        for (int ks = 0; ks < 4; ks++) {
            uint32_t a[4][4], b[NBL][4];
            #pragma unroll
            for (int mi = 0; mi < 4; mi++)
                ldsm4(a[mi], stA + mi*16*ROWB + ks*32);
            #pragma unroll
            for (int pi = 0; pi < NBL; pi++)
                ldsm4(b[pi], stB + pi*16*ROWB + ks*32);
            #pragma unroll
            for (int mi = 0; mi < 4; mi++)
                #pragma unroll
                for (int ni = 0; ni < NFR; ni++) {
                    int pi = ni >> 1, j = (ni & 1) * 2;
                    mma16(acc[mi][ni], a[mi], b[pi][j], b[pi][j+1]);
                }
        }
    }

    int g = lane >> 2, t4 = lane & 3;
    int warpN0 = tileN + wn*WN;
    #pragma unroll
    for (int mi = 0; mi < 4; mi++) {
        int r0 = tileM + wm*64 + mi*16 + g;
        #pragma unroll
        for (int ni = 0; ni < NFR; ni++) {
            int c = warpN0 + ni*8 + 2*t4;
            if (c >= N) continue;
            float2 v0 = make_float2(acc[mi][ni][0], acc[mi][ni][1]);
            float2 v1 = make_float2(acc[mi][ni][2], acc[mi][ni][3]);
            if (EPI == 2) {
                float b0 = bias[c], b1 = bias[c+1];
                v0.x += b0; v0.y += b1; v1.x += b0; v1.y += b1;
                v0.x = (v0.x > 20.f) ? v0.x : log1pf(expf(v0.x));
                v0.y = (v0.y > 20.f) ? v0.y : log1pf(expf(v0.y));
                v1.x = (v1.x > 20.f) ? v1.x : log1pf(expf(v1.x));
                v1.y = (v1.y > 20.f) ? v1.y : log1pf(expf(v1.y));
                // transposed store: C[c][t], ldc = TTOK
                C[(size_t)c     * ldc + r0    ] = v0.x;
                C[(size_t)(c+1) * ldc + r0    ] = v0.y;
                C[(size_t)c     * ldc + r0 + 8] = v1.x;
                C[(size_t)(c+1) * ldc + r0 + 8] = v1.y;
            } else {
                float* p0 = C + (size_t)r0 * ldc + c;
                float* p1 = C + (size_t)(r0 + 8) * ldc + c;
                if (EPI == 1) {
                    float2 o0 = *(float2*)p0, o1 = *(float2*)p1;
                    v0.x += o0.x; v0.y += o0.y; v1.x += o1.x; v1.y += o1.y;
                }
                *(float2*)p0 = v0;
                *(float2*)p1 = v1;
            }
        }
    }
}

#define SMEMB(BM,BN) (3 * ((BM) + (BN)) * ROWB)

// ----------------------------------------------------------
extern "C" void kernel_launch(void* const* d_in, const int* in_sizes, int n_in,
                              void* d_out, int out_size)
{
    const int*   tokens       = (const int*)  d_in[0];
    const float* embed        = (const float*)d_in[1];
    const float* norm_w       = (const float*)d_in[2];
    const float* in_proj_w    = (const float*)d_in[3];
    const float* conv_w       = (const float*)d_in[4];
    const float* conv_b       = (const float*)d_in[5];
    const float* x_proj_w     = (const float*)d_in[6];
    const float* dt_w         = (const float*)d_in[7];
    const float* dt_b         = (const float*)d_in[8];
    const float* A_log        = (const float*)d_in[9];
    const float* D_skip       = (const float*)d_in[10];
    const float* out_proj_w   = (const float*)d_in[11];
    const float* final_norm_w = (const float*)d_in[12];
    float* out = (float*)d_out;

    float *h, *xz, *xct, *dtt, *Bt, *Ct, *xpp, *opp, *Ps, *Hs;
    __half *xnf,*xcf,*xdf,*yf;
    __half *winf,*woutf,*wxpf,*wdtf,*wembf;
    cudaGetSymbolAddress((void**)&h,    g_h);
    cudaGetSymbolAddress((void**)&xz,   g_xz);
    cudaGetSymbolAddress((void**)&xct,  g_xct);
    cudaGetSymbolAddress((void**)&dtt,  g_dtt);
    cudaGetSymbolAddress((void**)&Bt,   g_Bt);
    cudaGetSymbolAddress((void**)&Ct,   g_Ct);
    cudaGetSymbolAddress((void**)&xpp,  g_xpp);
    cudaGetSymbolAddress((void**)&opp,  g_opp);
    cudaGetSymbolAddress((void**)&Ps,   g_Pseg);
    cudaGetSymbolAddress((void**)&Hs,   g_Hseg);
    cudaGetSymbolAddress((void**)&xnf,  g_xn_f);
    cudaGetSymbolAddress((void**)&xcf,  g_xc_f);
    cudaGetSymbolAddress((void**)&xdf,  g_xd_f);
    cudaGetSymbolAddress((void**)&yf,   g_y_f);
    cudaGetSymbolAddress((void**)&winf, g_win_f);
    cudaGetSymbolAddress((void**)&woutf,g_wout_f);
    cudaGetSymbolAddress((void**)&wxpf, g_wxp_f);
    cudaGetSymbolAddress((void**)&wdtf, g_wdt_f);
    cudaGetSymbolAddress((void**)&wembf,g_wemb_f);

    cudaFuncSetAttribute((const void*)mma_gemm<0,128,128,2>, cudaFuncAttributeMaxDynamicSharedMemorySize, SMEMB(128,128));
    cudaFuncSetAttribute((const void*)mma_gemm<2,128,128,2>, cudaFuncAttributeMaxDynamicSharedMemorySize, SMEMB(128,128));

    {
        int n0 = NLAYER*2*DINNER*DMODEL/4;
        int n1 = NLAYER*DMODEL*DINNER/4;
        int n2 = NLAYER*XDBL_W*DINNER/4;
        int n3 = NLAYER*DINNER*DTRANK/4;
        int n4 = VOCAB*DMODEL/4;
        int tot = n0 + n1 + n2 + n3 + n4;
        cvt_all_k<<<(tot+255)/256, 256>>>(in_proj_w, winf, n0,
                                          out_proj_w, woutf, n1,
                                          x_proj_w,  wxpf,  n2,
                                          dt_w,      wdtf,  n3,
                                          embed,     wembf, n4);
    }

    embed_k<<<TTOK, 256>>>(tokens, embed, h);
    rmsnorm_k<<<TTOK, 256>>>(h, norm_w, xnf);   // layer 0 entry norm

    for (int L = 0; L < NLAYER; L++) {
        mma_gemm<0,128,128,2><<<dim3(2*DINNER/128, TTOK/128), 256, SMEMB(128,128)>>>(
            xnf, DMODEL, winf + (size_t)L * 2*DINNER*DMODEL, DMODEL,
            xz, 2*DINNER, nullptr, 2*DINNER, DMODEL, 0);

        conv_silu_k<<<((TTOK/4)*DINNER + 255)/256, 256>>>(
            xz, conv_w + (size_t)L * DINNER*DCONV, conv_b + (size_t)L * DINNER,
            xct, xcf);

        mma_gemm<0,128,128,2><<<dim3(1, TTOK/128, XP_SPLIT), 256, SMEMB(128,128)>>>(
            xcf, DINNER, wxpf + (size_t)L * XDBL_W*DINNER, DINNER,
            xpp, XDBL_W, nullptr, XDBL_W, DINNER/XP_SPLIT, TTOK*XDBL_W);

        reduce_xp_k<<<(TTOK*XDBL_W + 255)/256, 256>>>(xpp, xdf, Bt, Ct);

        // dt: softplus(+bias), TRANSPOSED output dtt[c][t] (ldc = TTOK)
        mma_gemm<2,128,128,2><<<dim3(DINNER/128, TTOK/128), 256, SMEMB(128,128)>>>(
            xdf, XDBL_W, wdtf + (size_t)L * DINNER*DTRANK, DTRANK,
            dtt, TTOK, dt_b + (size_t)L * DINNER, DINNER, DTRANK, 0);

        scan1_k<<<BATCH*128*SEG, 256>>>(Bt, dtt, xct,
                                        A_log + (size_t)L * DINNER*DSTATE, Ps, Hs);
        scan2_k<<<BATCH*128*SEG, 256>>>(Bt, Ct, dtt, xct, xz,
                                        A_log + (size_t)L * DINNER*DSTATE,
                                        D_skip + (size_t)L * DINNER, Ps, Hs, yf);

        mma_gemm<0,128,128,2><<<dim3(DMODEL/128, TTOK/128, OP_SPLIT), 256, SMEMB(128,128)>>>(
            yf, DINNER, woutf + (size_t)L * DMODEL*DINNER, DINNER,
            opp, DMODEL, nullptr, DMODEL, DINNER/OP_SPLIT, TTOK*DMODEL);

        const float* wn = (L < NLAYER-1) ? (norm_w + (size_t)(L+1) * DMODEL)
                                         : final_norm_w;
        resid_norm_k<<<TTOK, 256>>>(opp, h, wn, xnf);
    }

    mma_gemm<0,128,128,2><<<dim3(VOCAB/128, TTOK/128), 256, SMEMB(128,128)>>>(
        xnf, DMODEL, wembf, DMODEL, out, VOCAB, nullptr, VOCAB, DMODEL, 0);
}

// round 16
// speedup vs baseline: 1.2084x; 1.2084x over previous
#include <cuda_runtime.h>
#include <cuda_fp16.h>
#include <math.h>
#include <stdint.h>

#define BATCH   2
#define SEQ     1024
#define DMODEL  1024
#define NLAYER  4
#define VOCAB   32000
#define DSTATE  16
#define DCONV   4
#define DINNER  2048
#define DTRANK  64
#define TTOK    (BATCH*SEQ)
#define XDBL_W  96
#define XP_SPLIT 8
#define OP_SPLIT 2
#define SEG     8
#define SEGLEN  (SEQ/SEG)    // 128

// -------- fp32 scratch --------
__device__ float g_h   [TTOK*DMODEL];
__device__ float g_xz  [TTOK*2*DINNER];
__device__ float g_xc  [TTOK*DINNER];
__device__ float g_xdbl[TTOK*XDBL_W];
__device__ float g_dt  [TTOK*DINNER];
__device__ float g_xpp [XP_SPLIT*TTOK*XDBL_W];
__device__ float g_opp [OP_SPLIT*TTOK*DMODEL];
__device__ float g_Pseg[BATCH*DINNER*DSTATE*SEG];
__device__ float g_Hseg[BATCH*DINNER*DSTATE*SEG];
// -------- fp16 activations --------
__device__ __half g_xn_f[TTOK*DMODEL];
__device__ __half g_xc_f[TTOK*DINNER];
__device__ __half g_xd_f[TTOK*XDBL_W];
__device__ __half g_y_f [TTOK*DINNER];
// -------- fp16 weights --------
__device__ __half g_win_f [NLAYER*2*DINNER*DMODEL];
__device__ __half g_wout_f[NLAYER*DMODEL*DINNER];
__device__ __half g_wxp_f [NLAYER*XDBL_W*DINNER];
__device__ __half g_wdt_f [NLAYER*DINNER*DTRANK];
__device__ __half g_wemb_f[VOCAB*DMODEL];

// ---------------- helpers ----------------
__device__ __forceinline__ void cp16(uint32_t dst, const void* src, int srcBytes) {
    asm volatile("cp.async.cg.shared.global [%0], [%1], 16, %2;"
                 :: "r"(dst), "l"(src), "r"(srcBytes));
}
__device__ __forceinline__ void cp_commit() { asm volatile("cp.async.commit_group;"); }
template<int N> __device__ __forceinline__ void cp_wait() {
    asm volatile("cp.async.wait_group %0;" :: "n"(N));
}
__device__ __forceinline__ void ldsm4(uint32_t* r, uint32_t addr) {
    asm volatile("ldmatrix.sync.aligned.m8n8.x4.shared.b16 {%0,%1,%2,%3}, [%4];"
                 : "=r"(r[0]), "=r"(r[1]), "=r"(r[2]), "=r"(r[3]) : "r"(addr));
}
__device__ __forceinline__ void mma16(float* d, const uint32_t* a, uint32_t b0, uint32_t b1) {
    asm volatile(
        "mma.sync.aligned.m16n8k16.row.col.f32.f16.f16.f32 "
        "{%0,%1,%2,%3}, {%4,%5,%6,%7}, {%8,%9}, {%0,%1,%2,%3};\n"
        : "+f"(d[0]), "+f"(d[1]), "+f"(d[2]), "+f"(d[3])
        : "r"(a[0]), "r"(a[1]), "r"(a[2]), "r"(a[3]), "r"(b0), "r"(b1));
}
__device__ __forceinline__ uint32_t pack2h(float a, float b) {
    __half2 p = __floats2half2_rn(a, b);
    return *(uint32_t*)&p;
}

// ---------------- elementwise kernels ----------------
__global__ void cvt_all_k(const float* __restrict__ s0, __half* __restrict__ d0, int n0,
                          const float* __restrict__ s1, __half* __restrict__ d1, int n1,
                          const float* __restrict__ s2, __half* __restrict__ d2, int n2,
                          const float* __restrict__ s3, __half* __restrict__ d3, int n3,
                          const float* __restrict__ s4, __half* __restrict__ d4, int n4)
{
    int i = blockIdx.x * blockDim.x + threadIdx.x;
    const float* s; __half* d; int j = i;
    if (i < n0)                       { s = s0; d = d0; }
    else if ((j -= n0) < n1)          { s = s1; d = d1; }
    else if ((j -= n1) < n2)          { s = s2; d = d2; }
    else if ((j -= n2) < n3)          { s = s3; d = d3; }
    else if ((j -= n3) < n4)          { s = s4; d = d4; }
    else return;
    float4 v = ((const float4*)s)[j];
    uint2 p;
    p.x = pack2h(v.x, v.y);
    p.y = pack2h(v.z, v.w);
    ((uint2*)d)[j] = p;
}

__global__ void embed_k(const int* __restrict__ tok, const float* __restrict__ emb,
                        float* __restrict__ out)
{
    int t = blockIdx.x;
    int row = tok[t];
    ((float4*)(out + (size_t)t * DMODEL))[threadIdx.x] =
        ((const float4*)(emb + (size_t)row * DMODEL))[threadIdx.x];
}

__global__ void rmsnorm_k(const float* __restrict__ x, const float* __restrict__ w,
                          __half* __restrict__ oh)
{
    int t = blockIdx.x;
    int tid = threadIdx.x;
    float4 v = ((const float4*)(x + (size_t)t * DMODEL))[tid];
    float ss = v.x*v.x + v.y*v.y + v.z*v.z + v.w*v.w;
    __shared__ float sbuf[8];
    #pragma unroll
    for (int o = 16; o; o >>= 1) ss += __shfl_xor_sync(0xffffffffu, ss, o);
    int warp = tid >> 5, lane = tid & 31;
    if (lane == 0) sbuf[warp] = ss;
    __syncthreads();
    if (warp == 0) {
        float s2 = (lane < 8) ? sbuf[lane] : 0.f;
        #pragma unroll
        for (int o = 4; o; o >>= 1) s2 += __shfl_xor_sync(0xffffffffu, s2, o);
        if (lane == 0) sbuf[0] = rsqrtf(s2 * (1.0f / DMODEL) + 1e-5f);
    }
    __syncthreads();
    float r = sbuf[0];
    float4 wv = ((const float4*)w)[tid];
    uint2 p;
    p.x = pack2h(v.x*r*wv.x, v.y*r*wv.y);
    p.y = pack2h(v.z*r*wv.z, v.w*r*wv.w);
    ((uint2*)(oh + (size_t)t * DMODEL))[tid] = p;
}

// fused: h += opp0 + opp1; xnf = rmsnorm(h, w) in fp16
__global__ void resid_norm_k(const float* __restrict__ parts, float* __restrict__ h,
                             const float* __restrict__ w, __half* __restrict__ oh)
{
    int t = blockIdx.x;
    int tid = threadIdx.x;
    size_t ro = (size_t)t * 256 + tid;
    float4 v = ((const float4*)h)[ro];
    float4 a = ((const float4*)parts)[ro];
    float4 b = ((const float4*)(parts + (size_t)TTOK * DMODEL))[ro];
    v.x += a.x + b.x; v.y += a.y + b.y;
    v.z += a.z + b.z; v.w += a.w + b.w;
    ((float4*)h)[ro] = v;

    float ss = v.x*v.x + v.y*v.y + v.z*v.z + v.w*v.w;
    __shared__ float sbuf[8];
    #pragma unroll
    for (int o = 16; o; o >>= 1) ss += __shfl_xor_sync(0xffffffffu, ss, o);
    int warp = tid >> 5, lane = tid & 31;
    if (lane == 0) sbuf[warp] = ss;
    __syncthreads();
    if (warp == 0) {
        float s2 = (lane < 8) ? sbuf[lane] : 0.f;
        #pragma unroll
        for (int o = 4; o; o >>= 1) s2 += __shfl_xor_sync(0xffffffffu, s2, o);
        if (lane == 0) sbuf[0] = rsqrtf(s2 * (1.0f / DMODEL) + 1e-5f);
    }
    __syncthreads();
    float r = sbuf[0];
    float4 wv = ((const float4*)w)[tid];
    uint2 p;
    p.x = pack2h(v.x*r*wv.x, v.y*r*wv.y);
    p.y = pack2h(v.z*r*wv.z, v.w*r*wv.w);
    ((uint2*)(oh + (size_t)t * DMODEL))[tid] = p;
}

// conv: 4 timesteps per thread; outputs [t][c] fp32 + fp16 (R14 layouts)
__global__ void conv_silu_k(const float* __restrict__ xz, const float* __restrict__ cw,
                            const float* __restrict__ cb, float* __restrict__ xc,
                            __half* __restrict__ xch)
{
    int idx = blockIdx.x * blockDim.x + threadIdx.x;
    if (idx >= (TTOK/4) * DINNER) return;
    int c  = idx % DINNER;
    int t4 = idx / DINNER;
    int t0 = t4 * 4;
    int l0 = t0 % SEQ;

    float4 w4 = *(const float4*)(cw + c * 4);
    float bias = cb[c];
    const size_t str = 2 * DINNER;

    float v[7];
    #pragma unroll
    for (int j = 0; j < 7; j++) {
        int l = l0 + j - 3;
        v[j] = (l >= 0) ? xz[(size_t)(t0 + j - 3) * str + c] : 0.f;
    }
    #pragma unroll
    for (int j = 0; j < 4; j++) {
        float acc = bias + w4.x * v[j] + w4.y * v[j+1] + w4.z * v[j+2] + w4.w * v[j+3];
        float s = 1.f / (1.f + expf(-acc));
        float o = acc * s;
        int t = t0 + j;
        xc[(size_t)t * DINNER + c] = o;
        xch[(size_t)t * DINNER + c] = __float2half_rn(o);
    }
}

__global__ void reduce_xp_k(const float* __restrict__ parts,
                            float* __restrict__ xdbl, __half* __restrict__ xdf)
{
    int i = blockIdx.x * blockDim.x + threadIdx.x;
    if (i >= TTOK * XDBL_W) return;
    float s = 0.f;
    #pragma unroll
    for (int p = 0; p < XP_SPLIT; p++)
        s += parts[(size_t)p * TTOK * XDBL_W + i];
    xdbl[i] = s;
    xdf[i] = __float2half_rn(s);
}

// ---------------- segmented selective scan, SMEM-STAGED ----------------
// grid: 2048 blocks = B(2) x cgrp(128) x seg(8), 256 thr = 16 chan x 16 state
// Stage dt/xc (128t x 16c) and B/C (128t x 16s) tiles in smem via coalesced
// float4 loads of the EXISTING [t][c] layouts; hot loop reads LDS broadcast.
__global__ __launch_bounds__(256)
void scan1_k(const float* __restrict__ xdbl, const float* __restrict__ dt,
             const float* __restrict__ xc,   const float* __restrict__ A_log,
             float* __restrict__ Pseg, float* __restrict__ Hseg)
{
    __shared__ float sdt[SEGLEN*16];
    __shared__ float sxc[SEGLEN*16];
    __shared__ float sB [SEGLEN*16];

    int tid = threadIdx.x;
    int s = tid & 15;
    int bid = blockIdx.x;
    int seg  = bid & 7;
    int cgrp = (bid >> 3) & 127;
    int b    = bid >> 10;
    int c0 = cgrp << 4;
    int cl = tid >> 4;
    int c = c0 + cl;
    int t0 = b * SEQ + seg * SEGLEN;

    // cooperative stage: 512 float4 per array, 2 per thread
    #pragma unroll
    for (int i = tid; i < SEGLEN*4; i += 256) {
        int tl = i >> 2, q = i & 3;
        ((float4*)sdt)[i] = *(const float4*)(dt + (size_t)(t0+tl)*DINNER + c0 + q*4);
        ((float4*)sxc)[i] = *(const float4*)(xc + (size_t)(t0+tl)*DINNER + c0 + q*4);
        ((float4*)sB)[i]  = *(const float4*)(xdbl + (size_t)(t0+tl)*XDBL_W + DTRANK + q*4);
    }
    __syncthreads();

    float A = -expf(A_log[(size_t)c * DSTATE + s]);
    float P = 1.f, H = 0.f;
    #pragma unroll 4
    for (int l = 0; l < SEGLEN; l++) {
        float dtv = sdt[l*16 + cl];
        float xv  = sxc[l*16 + cl];
        float Bv  = sB [l*16 + s];
        float dA = __expf(dtv * A);
        H = dA * H + (dtv * xv) * Bv;
        P *= dA;
    }
    int idx = ((((b * DINNER + c) << 4) + s) << 3) + seg;
    Pseg[idx] = P;
    Hseg[idx] = H;
}

__global__ __launch_bounds__(256)
void scan2_k(const float* __restrict__ xdbl, const float* __restrict__ dt,
             const float* __restrict__ xc,   const float* __restrict__ xz,
             const float* __restrict__ A_log, const float* __restrict__ Dsk,
             const float* __restrict__ Pseg,  const float* __restrict__ Hseg,
             __half* __restrict__ yh)
{
    __shared__ float sdt[SEGLEN*16];
    __shared__ float sxc[SEGLEN*16];
    __shared__ float sB [SEGLEN*16];
    __shared__ float sC [SEGLEN*16];

    int tid = threadIdx.x;
    int s = tid & 15;
    int bid = blockIdx.x;
    int seg  = bid & 7;
    int cgrp = (bid >> 3) & 127;
    int b    = bid >> 10;
    int c0 = cgrp << 4;
    int cl = tid >> 4;
    int c = c0 + cl;
    int t0 = b * SEQ + seg * SEGLEN;

    #pragma unroll
    for (int i = tid; i < SEGLEN*4; i += 256) {
        int tl = i >> 2, q = i & 3;
        ((float4*)sdt)[i] = *(const float4*)(dt + (size_t)(t0+tl)*DINNER + c0 + q*4);
        ((float4*)sxc)[i] = *(const float4*)(xc + (size_t)(t0+tl)*DINNER + c0 + q*4);
        ((float4*)sB)[i]  = *(const float4*)(xdbl + (size_t)(t0+tl)*XDBL_W + DTRANK + q*4);
        ((float4*)sC)[i]  = *(const float4*)(xdbl + (size_t)(t0+tl)*XDBL_W + DTRANK + DSTATE + q*4);
    }
    __syncthreads();

    float A = -expf(A_log[(size_t)c * DSTATE + s]);
    float dval = Dsk[c];
    bool lane0 = (s == 0);

    int base = (((b * DINNER + c) << 4) + s) << 3;
    float h = 0.f;
    for (int j = 0; j < seg; j++)
        h = Pseg[base + j] * h + Hseg[base + j];

    #pragma unroll 4
    for (int l = 0; l < SEGLEN; l++) {
        float dtv = sdt[l*16 + cl];
        float xv  = sxc[l*16 + cl];
        float Bv  = sB [l*16 + s];
        float Cv  = sC [l*16 + s];
        float dA = __expf(dtv * A);
        h = dA * h + (dtv * xv) * Bv;
        float p = h * Cv;
        p += __shfl_xor_sync(0xffffffffu, p, 8);
        p += __shfl_xor_sync(0xffffffffu, p, 4);
        p += __shfl_xor_sync(0xffffffffu, p, 2);
        p += __shfl_xor_sync(0xffffffffu, p, 1);
        if (lane0) {
            int t = t0 + l;
            float z = xz[(size_t)t * (2*DINNER) + DINNER + c];
            float sg = 1.f / (1.f + __expf(-z));
            yh[(size_t)t * DINNER + c] = __float2half_rn((p + dval * xv) * (z * sg));
        }
    }
}

// ----------------------------------------------------------
// FP16 HMMA GEMM (NT). EPI: 0=store 1=accum 2=softplus+bias
// ----------------------------------------------------------
#define KCH     64
#define ROWB    144

template<int EPI, int BM, int BN, int MB>
__global__ __launch_bounds__(256, MB)
void mma_gemm(const __half* __restrict__ A, int lda,
              const __half* __restrict__ W, int ldw,
              float* __restrict__ C, int ldc,
              const float* __restrict__ bias,
              int N, int K, int zstride)
{
    constexpr int WM    = BM / 64;
    constexpr int WNW   = 8 / WM;
    constexpr int WN    = BN / WNW;
    constexpr int NFR   = WN / 8;
    constexpr int NBL   = WN / 16;
    constexpr int TILEA = BM * ROWB;
    constexpr int TILEB = BN * ROWB;
    constexpr int STAGE = TILEA + TILEB;
    constexpr int NTASK = (BM + BN) * 8;

    extern __shared__ char smem[];
    uint32_t sb = (uint32_t)__cvta_generic_to_shared(smem);

    int tid = threadIdx.x, lane = tid & 31, warp = tid >> 5;
    int wm = warp % WM;
    int wn = warp / WM;
    int tileM = blockIdx.y * BM, tileN = blockIdx.x * BN;

    int z = blockIdx.z;
    A += (size_t)z * K;
    W += (size_t)z * K;
    C += (size_t)z * zstride;

    float acc[4][NFR][4];
    #pragma unroll
    for (int mi = 0; mi < 4; mi++)
        #pragma unroll
        for (int ni = 0; ni < NFR; ni++)
            #pragma unroll
            for (int e = 0; e < 4; e++) acc[mi][ni][e] = 0.f;

    const int iters = K / KCH;

    uint32_t laneAoff = (uint32_t)((wm*64 + (lane & 15)) * ROWB + ((lane >> 4) & 1) * 16);
    uint32_t laneBoff = (uint32_t)((wn*WN + (lane & 7) + ((lane >= 16) ? 8 : 0)) * ROWB
                                   + ((lane >> 3) & 1) * 16);

    auto load_chunk = [&](int s, int it) {
        int k0 = it * KCH;
        uint32_t sbase = sb + (uint32_t)(s * STAGE);
        #pragma unroll
        for (int i = 0; i < NTASK/256; i++) {
            int task = tid + i * 256;
            if (task < BM*8) {
                int r = task >> 3, c = task & 7;
                cp16(sbase + (uint32_t)(r * ROWB + c * 16),
                     A + (size_t)(tileM + r) * lda + k0 + c * 8, 16);
            } else {
                int t2 = task - BM*8;
                int r = t2 >> 3, c = t2 & 7;
                int wr = tileN + r;
                const __half* src = W + (size_t)(wr < N ? wr : 0) * ldw + k0 + c * 8;
                cp16(sbase + (uint32_t)(TILEA + r * ROWB + c * 16),
                     src, wr < N ? 16 : 0);
            }
        }
        cp_commit();
    };

    if (iters > 0) load_chunk(0, 0);
    if (iters > 1) load_chunk(1, 1);

    for (int it = 0; it < iters; it++) {
        if (iters - 1 - it >= 1) cp_wait<1>();
        else                     cp_wait<0>();
        __syncthreads();
        if (it + 2 < iters) load_chunk((it + 2) % 3, it + 2);

        int s = it % 3;
        uint32_t stA = sb + s*STAGE + laneAoff;
        uint32_t stB = sb + s*STAGE + TILEA + laneBoff;

        #pragma unroll
        for (int ks = 0; ks < 4; ks++) {
            uint32_t a[4][4], b[NBL][4];
            #pragma unroll
            for (int mi = 0; mi < 4; mi++)
                ldsm4(a[mi], stA + mi*16*ROWB + ks*32);
            #pragma unroll
            for (int pi = 0; pi < NBL; pi++)
                ldsm4(b[pi], stB + pi*16*ROWB + ks*32);
            #pragma unroll
            for (int mi = 0; mi < 4; mi++)
                #pragma unroll
                for (int ni = 0; ni < NFR; ni++) {
                    int pi = ni >> 1, j = (ni & 1) * 2;
                    mma16(acc[mi][ni], a[mi], b[pi][j], b[pi][j+1]);
                }
        }
    }

    int g = lane >> 2, t4 = lane & 3;
    int warpN0 = tileN + wn*WN;
    #pragma unroll
    for (int mi = 0; mi < 4; mi++) {
        int r0 = tileM + wm*64 + mi*16 + g;
        #pragma unroll
        for (int ni = 0; ni < NFR; ni++) {
            int c = warpN0 + ni*8 + 2*t4;
            if (c >= N) continue;
            float2 v0 = make_float2(acc[mi][ni][0], acc[mi][ni][1]);
            float2 v1 = make_float2(acc[mi][ni][2], acc[mi][ni][3]);
            float* p0 = C + (size_t)r0 * ldc + c;
            float* p1 = C + (size_t)(r0 + 8) * ldc + c;
            if (EPI == 1) {
                float2 o0 = *(float2*)p0, o1 = *(float2*)p1;
                v0.x += o0.x; v0.y += o0.y; v1.x += o1.x; v1.y += o1.y;
            } else if (EPI == 2) {
                float b0 = bias[c], b1 = bias[c+1];
                v0.x += b0; v0.y += b1; v1.x += b0; v1.y += b1;
                v0.x = (v0.x > 20.f) ? v0.x : log1pf(expf(v0.x));
                v0.y = (v0.y > 20.f) ? v0.y : log1pf(expf(v0.y));
                v1.x = (v1.x > 20.f) ? v1.x : log1pf(expf(v1.x));
                v1.y = (v1.y > 20.f) ? v1.y : log1pf(expf(v1.y));
            }
            *(float2*)p0 = v0;
            *(float2*)p1 = v1;
        }
    }
}

#define SMEMB(BM,BN) (3 * ((BM) + (BN)) * ROWB)

// ----------------------------------------------------------
extern "C" void kernel_launch(void* const* d_in, const int* in_sizes, int n_in,
                              void* d_out, int out_size)
{
    const int*   tokens       = (const int*)  d_in[0];
    const float* embed        = (const float*)d_in[1];
    const float* norm_w       = (const float*)d_in[2];
    const float* in_proj_w    = (const float*)d_in[3];
    const float* conv_w       = (const float*)d_in[4];
    const float* conv_b       = (const float*)d_in[5];
    const float* x_proj_w     = (const float*)d_in[6];
    const float* dt_w         = (const float*)d_in[7];
    const float* dt_b         = (const float*)d_in[8];
    const float* A_log        = (const float*)d_in[9];
    const float* D_skip       = (const float*)d_in[10];
    const float* out_proj_w   = (const float*)d_in[11];
    const float* final_norm_w = (const float*)d_in[12];
    float* out = (float*)d_out;

    float *h, *xz, *xc, *xdbl, *dts, *xpp, *opp, *Ps, *Hs;
    __half *xnf,*xcf,*xdf,*yf;
    __half *winf,*woutf,*wxpf,*wdtf,*wembf;
    cudaGetSymbolAddress((void**)&h,    g_h);
    cudaGetSymbolAddress((void**)&xz,   g_xz);
    cudaGetSymbolAddress((void**)&xc,   g_xc);
    cudaGetSymbolAddress((void**)&xdbl, g_xdbl);
    cudaGetSymbolAddress((void**)&dts,  g_dt);
    cudaGetSymbolAddress((void**)&xpp,  g_xpp);
    cudaGetSymbolAddress((void**)&opp,  g_opp);
    cudaGetSymbolAddress((void**)&Ps,   g_Pseg);
    cudaGetSymbolAddress((void**)&Hs,   g_Hseg);
    cudaGetSymbolAddress((void**)&xnf,  g_xn_f);
    cudaGetSymbolAddress((void**)&xcf,  g_xc_f);
    cudaGetSymbolAddress((void**)&xdf,  g_xd_f);
    cudaGetSymbolAddress((void**)&yf,   g_y_f);
    cudaGetSymbolAddress((void**)&winf, g_win_f);
    cudaGetSymbolAddress((void**)&woutf,g_wout_f);
    cudaGetSymbolAddress((void**)&wxpf, g_wxp_f);
    cudaGetSymbolAddress((void**)&wdtf, g_wdt_f);
    cudaGetSymbolAddress((void**)&wembf,g_wemb_f);

    cudaFuncSetAttribute((const void*)mma_gemm<0,128,128,2>, cudaFuncAttributeMaxDynamicSharedMemorySize, SMEMB(128,128));
    cudaFuncSetAttribute((const void*)mma_gemm<2,128,128,2>, cudaFuncAttributeMaxDynamicSharedMemorySize, SMEMB(128,128));

    {
        int n0 = NLAYER*2*DINNER*DMODEL/4;
        int n1 = NLAYER*DMODEL*DINNER/4;
        int n2 = NLAYER*XDBL_W*DINNER/4;
        int n3 = NLAYER*DINNER*DTRANK/4;
        int n4 = VOCAB*DMODEL/4;
        int tot = n0 + n1 + n2 + n3 + n4;
        cvt_all_k<<<(tot+255)/256, 256>>>(in_proj_w, winf, n0,
                                          out_proj_w, woutf, n1,
                                          x_proj_w,  wxpf,  n2,
                                          dt_w,      wdtf,  n3,
                                          embed,     wembf, n4);
    }

    embed_k<<<TTOK, 256>>>(tokens, embed, h);
    rmsnorm_k<<<TTOK, 256>>>(h, norm_w, xnf);   // layer 0 entry norm

    for (int L = 0; L < NLAYER; L++) {
        mma_gemm<0,128,128,2><<<dim3(2*DINNER/128, TTOK/128), 256, SMEMB(128,128)>>>(
            xnf, DMODEL, winf + (size_t)L * 2*DINNER*DMODEL, DMODEL,
            xz, 2*DINNER, nullptr, 2*DINNER, DMODEL, 0);

        conv_silu_k<<<((TTOK/4)*DINNER + 255)/256, 256>>>(
            xz, conv_w + (size_t)L * DINNER*DCONV, conv_b + (size_t)L * DINNER,
            xc, xcf);

        mma_gemm<0,128,128,2><<<dim3(1, TTOK/128, XP_SPLIT), 256, SMEMB(128,128)>>>(
            xcf, DINNER, wxpf + (size_t)L * XDBL_W*DINNER, DINNER,
            xpp, XDBL_W, nullptr, XDBL_W, DINNER/XP_SPLIT, TTOK*XDBL_W);

        reduce_xp_k<<<(TTOK*XDBL_W + 255)/256, 256>>>(xpp, xdbl, xdf);

        mma_gemm<2,128,128,2><<<dim3(DINNER/128, TTOK/128), 256, SMEMB(128,128)>>>(
            xdf, XDBL_W, wdtf + (size_t)L * DINNER*DTRANK, DTRANK,
            dts, DINNER, dt_b + (size_t)L * DINNER, DINNER, DTRANK, 0);

        scan1_k<<<BATCH*128*SEG, 256>>>(xdbl, dts, xc,
                                        A_log + (size_t)L * DINNER*DSTATE, Ps, Hs);
        scan2_k<<<BATCH*128*SEG, 256>>>(xdbl, dts, xc, xz,
                                        A_log + (size_t)L * DINNER*DSTATE,
                                        D_skip + (size_t)L * DINNER, Ps, Hs, yf);

        mma_gemm<0,128,128,2><<<dim3(DMODEL/128, TTOK/128, OP_SPLIT), 256, SMEMB(128,128)>>>(
            yf, DINNER, woutf + (size_t)L * DMODEL*DINNER, DINNER,
            opp, DMODEL, nullptr, DMODEL, DINNER/OP_SPLIT, TTOK*DMODEL);

        const float* wn = (L < NLAYER-1) ? (norm_w + (size_t)(L+1) * DMODEL)
                                         : final_norm_w;
        resid_norm_k<<<TTOK, 256>>>(opp, h, wn, xnf);
    }

    mma_gemm<0,128,128,2><<<dim3(VOCAB/128, TTOK/128), 256, SMEMB(128,128)>>>(
        xnf, DMODEL, wembf, DMODEL, out, VOCAB, nullptr, VOCAB, DMODEL, 0);
}

// round 17
// speedup vs baseline: 1.4003x; 1.1588x over previous
#include <cuda_runtime.h>
#include <cuda_fp16.h>
#include <math.h>
#include <stdint.h>

#define BATCH   2
#define SEQ     1024
#define DMODEL  1024
#define NLAYER  4
#define VOCAB   32000
#define DSTATE  16
#define DCONV   4
#define DINNER  2048
#define DTRANK  64
#define TTOK    (BATCH*SEQ)
#define XDBL_W  96
#define XP_SPLIT 8
#define OP_SPLIT 2
#define SEG     8
#define SEGLEN  (SEQ/SEG)    // 128
#define SCBLK   (BATCH*SEG*(DINNER/256))   // 128 scan blocks

// -------- fp32 scratch --------
__device__ float g_h   [TTOK*DMODEL];
__device__ float g_xz  [TTOK*2*DINNER];
__device__ float g_xc  [TTOK*DINNER];
__device__ float g_xdbl[TTOK*XDBL_W];
__device__ float g_dt  [TTOK*DINNER];
__device__ float g_xpp [XP_SPLIT*TTOK*XDBL_W];
__device__ float g_opp [OP_SPLIT*TTOK*DMODEL];
__device__ float g_Pseg[BATCH*SEG*DSTATE*DINNER];   // [b][seg][s][c]
__device__ float g_Hseg[BATCH*SEG*DSTATE*DINNER];
// -------- fp16 activations --------
__device__ __half g_xn_f[TTOK*DMODEL];
__device__ __half g_xc_f[TTOK*DINNER];
__device__ __half g_xd_f[TTOK*XDBL_W];
__device__ __half g_y_f [TTOK*DINNER];
// -------- fp16 weights --------
__device__ __half g_win_f [NLAYER*2*DINNER*DMODEL];
__device__ __half g_wout_f[NLAYER*DMODEL*DINNER];
__device__ __half g_wxp_f [NLAYER*XDBL_W*DINNER];
__device__ __half g_wdt_f [NLAYER*DINNER*DTRANK];
__device__ __half g_wemb_f[VOCAB*DMODEL];

// ---------------- helpers ----------------
__device__ __forceinline__ void cp16(uint32_t dst, const void* src, int srcBytes) {
    asm volatile("cp.async.cg.shared.global [%0], [%1], 16, %2;"
                 :: "r"(dst), "l"(src), "r"(srcBytes));
}
__device__ __forceinline__ void cp_commit() { asm volatile("cp.async.commit_group;"); }
template<int N> __device__ __forceinline__ void cp_wait() {
    asm volatile("cp.async.wait_group %0;" :: "n"(N));
}
__device__ __forceinline__ void ldsm4(uint32_t* r, uint32_t addr) {
    asm volatile("ldmatrix.sync.aligned.m8n8.x4.shared.b16 {%0,%1,%2,%3}, [%4];"
                 : "=r"(r[0]), "=r"(r[1]), "=r"(r[2]), "=r"(r[3]) : "r"(addr));
}
__device__ __forceinline__ void mma16(float* d, const uint32_t* a, uint32_t b0, uint32_t b1) {
    asm volatile(
        "mma.sync.aligned.m16n8k16.row.col.f32.f16.f16.f32 "
        "{%0,%1,%2,%3}, {%4,%5,%6,%7}, {%8,%9}, {%0,%1,%2,%3};\n"
        : "+f"(d[0]), "+f"(d[1]), "+f"(d[2]), "+f"(d[3])
        : "r"(a[0]), "r"(a[1]), "r"(a[2]), "r"(a[3]), "r"(b0), "r"(b1));
}
__device__ __forceinline__ uint32_t pack2h(float a, float b) {
    __half2 p = __floats2half2_rn(a, b);
    return *(uint32_t*)&p;
}

// ---------------- elementwise kernels ----------------
__global__ void cvt_all_k(const float* __restrict__ s0, __half* __restrict__ d0, int n0,
                          const float* __restrict__ s1, __half* __restrict__ d1, int n1,
                          const float* __restrict__ s2, __half* __restrict__ d2, int n2,
                          const float* __restrict__ s3, __half* __restrict__ d3, int n3,
                          const float* __restrict__ s4, __half* __restrict__ d4, int n4)
{
    int i = blockIdx.x * blockDim.x + threadIdx.x;
    const float* s; __half* d; int j = i;
    if (i < n0)                       { s = s0; d = d0; }
    else if ((j -= n0) < n1)          { s = s1; d = d1; }
    else if ((j -= n1) < n2)          { s = s2; d = d2; }
    else if ((j -= n2) < n3)          { s = s3; d = d3; }
    else if ((j -= n3) < n4)          { s = s4; d = d4; }
    else return;
    float4 v = ((const float4*)s)[j];
    uint2 p;
    p.x = pack2h(v.x, v.y);
    p.y = pack2h(v.z, v.w);
    ((uint2*)d)[j] = p;
}

__global__ void embed_k(const int* __restrict__ tok, const float* __restrict__ emb,
                        float* __restrict__ out)
{
    int t = blockIdx.x;
    int row = tok[t];
    ((float4*)(out + (size_t)t * DMODEL))[threadIdx.x] =
        ((const float4*)(emb + (size_t)row * DMODEL))[threadIdx.x];
}

__global__ void rmsnorm_k(const float* __restrict__ x, const float* __restrict__ w,
                          __half* __restrict__ oh)
{
    int t = blockIdx.x;
    int tid = threadIdx.x;
    float4 v = ((const float4*)(x + (size_t)t * DMODEL))[tid];
    float ss = v.x*v.x + v.y*v.y + v.z*v.z + v.w*v.w;
    __shared__ float sbuf[8];
    #pragma unroll
    for (int o = 16; o; o >>= 1) ss += __shfl_xor_sync(0xffffffffu, ss, o);
    int warp = tid >> 5, lane = tid & 31;
    if (lane == 0) sbuf[warp] = ss;
    __syncthreads();
    if (warp == 0) {
        float s2 = (lane < 8) ? sbuf[lane] : 0.f;
        #pragma unroll
        for (int o = 4; o; o >>= 1) s2 += __shfl_xor_sync(0xffffffffu, s2, o);
        if (lane == 0) sbuf[0] = rsqrtf(s2 * (1.0f / DMODEL) + 1e-5f);
    }
    __syncthreads();
    float r = sbuf[0];
    float4 wv = ((const float4*)w)[tid];
    uint2 p;
    p.x = pack2h(v.x*r*wv.x, v.y*r*wv.y);
    p.y = pack2h(v.z*r*wv.z, v.w*r*wv.w);
    ((uint2*)(oh + (size_t)t * DMODEL))[tid] = p;
}

// fused: h += opp0 + opp1; xnf = rmsnorm(h, w) in fp16
__global__ void resid_norm_k(const float* __restrict__ parts, float* __restrict__ h,
                             const float* __restrict__ w, __half* __restrict__ oh)
{
    int t = blockIdx.x;
    int tid = threadIdx.x;
    size_t ro = (size_t)t * 256 + tid;
    float4 v = ((const float4*)h)[ro];
    float4 a = ((const float4*)parts)[ro];
    float4 b = ((const float4*)(parts + (size_t)TTOK * DMODEL))[ro];
    v.x += a.x + b.x; v.y += a.y + b.y;
    v.z += a.z + b.z; v.w += a.w + b.w;
    ((float4*)h)[ro] = v;

    float ss = v.x*v.x + v.y*v.y + v.z*v.z + v.w*v.w;
    __shared__ float sbuf[8];
    #pragma unroll
    for (int o = 16; o; o >>= 1) ss += __shfl_xor_sync(0xffffffffu, ss, o);
    int warp = tid >> 5, lane = tid & 31;
    if (lane == 0) sbuf[warp] = ss;
    __syncthreads();
    if (warp == 0) {
        float s2 = (lane < 8) ? sbuf[lane] : 0.f;
        #pragma unroll
        for (int o = 4; o; o >>= 1) s2 += __shfl_xor_sync(0xffffffffu, s2, o);
        if (lane == 0) sbuf[0] = rsqrtf(s2 * (1.0f / DMODEL) + 1e-5f);
    }
    __syncthreads();
    float r = sbuf[0];
    float4 wv = ((const float4*)w)[tid];
    uint2 p;
    p.x = pack2h(v.x*r*wv.x, v.y*r*wv.y);
    p.y = pack2h(v.z*r*wv.z, v.w*r*wv.w);
    ((uint2*)(oh + (size_t)t * DMODEL))[tid] = p;
}

// conv: 4 timesteps per thread
__global__ void conv_silu_k(const float* __restrict__ xz, const float* __restrict__ cw,
                            const float* __restrict__ cb, float* __restrict__ xc,
                            __half* __restrict__ xch)
{
    int idx = blockIdx.x * blockDim.x + threadIdx.x;
    if (idx >= (TTOK/4) * DINNER) return;
    int c  = idx % DINNER;
    int t4 = idx / DINNER;
    int t0 = t4 * 4;
    int l0 = t0 % SEQ;

    float4 w4 = *(const float4*)(cw + c * 4);
    float bias = cb[c];
    const size_t str = 2 * DINNER;

    float v[7];
    #pragma unroll
    for (int j = 0; j < 7; j++) {
        int l = l0 + j - 3;
        v[j] = (l >= 0) ? xz[(size_t)(t0 + j - 3) * str + c] : 0.f;
    }
    #pragma unroll
    for (int j = 0; j < 4; j++) {
        float acc = bias + w4.x * v[j] + w4.y * v[j+1] + w4.z * v[j+2] + w4.w * v[j+3];
        float s = 1.f / (1.f + expf(-acc));
        float o = acc * s;
        int t = t0 + j;
        xc[(size_t)t * DINNER + c] = o;
        xch[(size_t)t * DINNER + c] = __float2half_rn(o);
    }
}

__global__ void reduce_xp_k(const float* __restrict__ parts,
                            float* __restrict__ xdbl, __half* __restrict__ xdf)
{
    int i = blockIdx.x * blockDim.x + threadIdx.x;
    if (i >= TTOK * XDBL_W) return;
    float s = 0.f;
    #pragma unroll
    for (int p = 0; p < XP_SPLIT; p++)
        s += parts[(size_t)p * TTOK * XDBL_W + i];
    xdbl[i] = s;
    xdf[i] = __float2half_rn(s);
}

// ---------------- segmented scan: THREAD-PER-CHANNEL (16 states in regs) ----
// grid: 128 blocks = b(2) x seg(8) x cgrp(8); 256 threads = 256 channels.
// Loads: dt/xc coalesced scalar; B/C broadcast float4; NO shuffles.
__global__ __launch_bounds__(256)
void scan1_k(const float* __restrict__ xdbl, const float* __restrict__ dt,
             const float* __restrict__ xc,   const float* __restrict__ A_log,
             float* __restrict__ Pseg, float* __restrict__ Hseg)
{
    int tid = threadIdx.x;
    int bid = blockIdx.x;
    int cgrp = bid & 7;
    int seg  = (bid >> 3) & 7;
    int b    = bid >> 6;
    int c = (cgrp << 8) + tid;

    float A[DSTATE], h[DSTATE], Pp[DSTATE];
    #pragma unroll
    for (int s = 0; s < DSTATE; s++) {
        A[s] = -expf(A_log[(size_t)c * DSTATE + s]);
        h[s] = 0.f;
        Pp[s] = 1.f;
    }

    int t0 = b * SEQ + seg * SEGLEN;
    for (int l = 0; l < SEGLEN; l++) {
        int t = t0 + l;
        float dtv = dt[(size_t)t * DINNER + c];
        float xv  = xc[(size_t)t * DINNER + c];
        float u = dtv * xv;
        const float4* Bp = (const float4*)(xdbl + (size_t)t * XDBL_W + DTRANK);
        float4 B0 = Bp[0], B1 = Bp[1], B2 = Bp[2], B3 = Bp[3];
        const float* Bv = (const float*)&B0;   // B0..B3 contiguous on stack? no —
        float Barr[16] = {B0.x,B0.y,B0.z,B0.w, B1.x,B1.y,B1.z,B1.w,
                          B2.x,B2.y,B2.z,B2.w, B3.x,B3.y,B3.z,B3.w};
        (void)Bv;
        #pragma unroll
        for (int s = 0; s < DSTATE; s++) {
            float dA = __expf(dtv * A[s]);
            h[s] = dA * h[s] + u * Barr[s];
            Pp[s] *= dA;
        }
    }
    size_t base = ((size_t)(b * SEG + seg) * DSTATE) * DINNER + c;
    #pragma unroll
    for (int s = 0; s < DSTATE; s++) {
        Pseg[base + (size_t)s * DINNER] = Pp[s];
        Hseg[base + (size_t)s * DINNER] = h[s];
    }
}

__global__ __launch_bounds__(256)
void scan2_k(const float* __restrict__ xdbl, const float* __restrict__ dt,
             const float* __restrict__ xc,   const float* __restrict__ xz,
             const float* __restrict__ A_log, const float* __restrict__ Dsk,
             const float* __restrict__ Pseg,  const float* __restrict__ Hseg,
             __half* __restrict__ yh)
{
    int tid = threadIdx.x;
    int bid = blockIdx.x;
    int cgrp = bid & 7;
    int seg  = (bid >> 3) & 7;
    int b    = bid >> 6;
    int c = (cgrp << 8) + tid;

    float A[DSTATE], h[DSTATE];
    #pragma unroll
    for (int s = 0; s < DSTATE; s++) {
        A[s] = -expf(A_log[(size_t)c * DSTATE + s]);
        h[s] = 0.f;
    }
    float dval = Dsk[c];

    // fold predecessor segments (coalesced reads)
    for (int j = 0; j < seg; j++) {
        size_t base = ((size_t)(b * SEG + j) * DSTATE) * DINNER + c;
        #pragma unroll
        for (int s = 0; s < DSTATE; s++) {
            float P = Pseg[base + (size_t)s * DINNER];
            float H = Hseg[base + (size_t)s * DINNER];
            h[s] = P * h[s] + H;
        }
    }

    int t0 = b * SEQ + seg * SEGLEN;
    for (int l = 0; l < SEGLEN; l++) {
        int t = t0 + l;
        float dtv = dt[(size_t)t * DINNER + c];
        float xv  = xc[(size_t)t * DINNER + c];
        float u = dtv * xv;
        const float4* Bp = (const float4*)(xdbl + (size_t)t * XDBL_W + DTRANK);
        float4 B0 = Bp[0], B1 = Bp[1], B2 = Bp[2], B3 = Bp[3];
        float4 C0 = Bp[4], C1 = Bp[5], C2 = Bp[6], C3 = Bp[7];
        float Barr[16] = {B0.x,B0.y,B0.z,B0.w, B1.x,B1.y,B1.z,B1.w,
                          B2.x,B2.y,B2.z,B2.w, B3.x,B3.y,B3.z,B3.w};
        float Carr[16] = {C0.x,C0.y,C0.z,C0.w, C1.x,C1.y,C1.z,C1.w,
                          C2.x,C2.y,C2.z,C2.w, C3.x,C3.y,C3.z,C3.w};
        float y = 0.f;
        #pragma unroll
        for (int s = 0; s < DSTATE; s++) {
            float dA = __expf(dtv * A[s]);
            h[s] = dA * h[s] + u * Barr[s];
            y += h[s] * Carr[s];
        }
        float z = xz[(size_t)t * (2*DINNER) + DINNER + c];
        float sg = 1.f / (1.f + __expf(-z));
        yh[(size_t)t * DINNER + c] = __float2half_rn((y + dval * xv) * (z * sg));
    }
}

// ----------------------------------------------------------
// FP16 HMMA GEMM (NT). EPI: 0=store 1=accum 2=softplus+bias
// ----------------------------------------------------------
#define KCH     64
#define ROWB    144

template<int EPI, int BM, int BN, int MB>
__global__ __launch_bounds__(256, MB)
void mma_gemm(const __half* __restrict__ A, int lda,
              const __half* __restrict__ W, int ldw,
              float* __restrict__ C, int ldc,
              const float* __restrict__ bias,
              int N, int K, int zstride)
{
    constexpr int WM    = BM / 64;
    constexpr int WNW   = 8 / WM;
    constexpr int WN    = BN / WNW;
    constexpr int NFR   = WN / 8;
    constexpr int NBL   = WN / 16;
    constexpr int TILEA = BM * ROWB;
    constexpr int TILEB = BN * ROWB;
    constexpr int STAGE = TILEA + TILEB;
    constexpr int NTASK = (BM + BN) * 8;

    extern __shared__ char smem[];
    uint32_t sb = (uint32_t)__cvta_generic_to_shared(smem);

    int tid = threadIdx.x, lane = tid & 31, warp = tid >> 5;
    int wm = warp % WM;
    int wn = warp / WM;
    int tileM = blockIdx.y * BM, tileN = blockIdx.x * BN;

    int z = blockIdx.z;
    A += (size_t)z * K;
    W += (size_t)z * K;
    C += (size_t)z * zstride;

    float acc[4][NFR][4];
    #pragma unroll
    for (int mi = 0; mi < 4; mi++)
        #pragma unroll
        for (int ni = 0; ni < NFR; ni++)
            #pragma unroll
            for (int e = 0; e < 4; e++) acc[mi][ni][e] = 0.f;

    const int iters = K / KCH;

    uint32_t laneAoff = (uint32_t)((wm*64 + (lane & 15)) * ROWB + ((lane >> 4) & 1) * 16);
    uint32_t laneBoff = (uint32_t)((wn*WN + (lane & 7) + ((lane >= 16) ? 8 : 0)) * ROWB
                                   + ((lane >> 3) & 1) * 16);

    auto load_chunk = [&](int s, int it) {
        int k0 = it * KCH;
        uint32_t sbase = sb + (uint32_t)(s * STAGE);
        #pragma unroll
        for (int i = 0; i < NTASK/256; i++) {
            int task = tid + i * 256;
            if (task < BM*8) {
                int r = task >> 3, c = task & 7;
                cp16(sbase + (uint32_t)(r * ROWB + c * 16),
                     A + (size_t)(tileM + r) * lda + k0 + c * 8, 16);
            } else {
                int t2 = task - BM*8;
                int r = t2 >> 3, c = t2 & 7;
                int wr = tileN + r;
                const __half* src = W + (size_t)(wr < N ? wr : 0) * ldw + k0 + c * 8;
                cp16(sbase + (uint32_t)(TILEA + r * ROWB + c * 16),
                     src, wr < N ? 16 : 0);
            }
        }
        cp_commit();
    };

    if (iters > 0) load_chunk(0, 0);
    if (iters > 1) load_chunk(1, 1);

    for (int it = 0; it < iters; it++) {
        if (iters - 1 - it >= 1) cp_wait<1>();
        else                     cp_wait<0>();
        __syncthreads();
        if (it + 2 < iters) load_chunk((it + 2) % 3, it + 2);

        int s = it % 3;
        uint32_t stA = sb + s*STAGE + laneAoff;
        uint32_t stB = sb + s*STAGE + TILEA + laneBoff;

        #pragma unroll
        for (int ks = 0; ks < 4; ks++) {
            uint32_t a[4][4], b[NBL][4];
            #pragma unroll
            for (int mi = 0; mi < 4; mi++)
                ldsm4(a[mi], stA + mi*16*ROWB + ks*32);
            #pragma unroll
            for (int pi = 0; pi < NBL; pi++)
                ldsm4(b[pi], stB + pi*16*ROWB + ks*32);
            #pragma unroll
            for (int mi = 0; mi < 4; mi++)
                #pragma unroll
                for (int ni = 0; ni < NFR; ni++) {
                    int pi = ni >> 1, j = (ni & 1) * 2;
                    mma16(acc[mi][ni], a[mi], b[pi][j], b[pi][j+1]);
                }
        }
    }

    int g = lane >> 2, t4 = lane & 3;
    int warpN0 = tileN + wn*WN;
    #pragma unroll
    for (int mi = 0; mi < 4; mi++) {
        int r0 = tileM + wm*64 + mi*16 + g;
        #pragma unroll
        for (int ni = 0; ni < NFR; ni++) {
            int c = warpN0 + ni*8 + 2*t4;
            if (c >= N) continue;
            float2 v0 = make_float2(acc[mi][ni][0], acc[mi][ni][1]);
            float2 v1 = make_float2(acc[mi][ni][2], acc[mi][ni][3]);
            float* p0 = C + (size_t)r0 * ldc + c;
            float* p1 = C + (size_t)(r0 + 8) * ldc + c;
            if (EPI == 1) {
                float2 o0 = *(float2*)p0, o1 = *(float2*)p1;
                v0.x += o0.x; v0.y += o0.y; v1.x += o1.x; v1.y += o1.y;
            } else if (EPI == 2) {
                float b0 = bias[c], b1 = bias[c+1];
                v0.x += b0; v0.y += b1; v1.x += b0; v1.y += b1;
                v0.x = (v0.x > 20.f) ? v0.x : log1pf(expf(v0.x));
                v0.y = (v0.y > 20.f) ? v0.y : log1pf(expf(v0.y));
                v1.x = (v1.x > 20.f) ? v1.x : log1pf(expf(v1.x));
                v1.y = (v1.y > 20.f) ? v1.y : log1pf(expf(v1.y));
            }
            *(float2*)p0 = v0;
            *(float2*)p1 = v1;
        }
    }
}

#define SMEMB(BM,BN) (3 * ((BM) + (BN)) * ROWB)

// ----------------------------------------------------------
extern "C" void kernel_launch(void* const* d_in, const int* in_sizes, int n_in,
                              void* d_out, int out_size)
{
    const int*   tokens       = (const int*)  d_in[0];
    const float* embed        = (const float*)d_in[1];
    const float* norm_w       = (const float*)d_in[2];
    const float* in_proj_w    = (const float*)d_in[3];
    const float* conv_w       = (const float*)d_in[4];
    const float* conv_b       = (const float*)d_in[5];
    const float* x_proj_w     = (const float*)d_in[6];
    const float* dt_w         = (const float*)d_in[7];
    const float* dt_b         = (const float*)d_in[8];
    const float* A_log        = (const float*)d_in[9];
    const float* D_skip       = (const float*)d_in[10];
    const float* out_proj_w   = (const float*)d_in[11];
    const float* final_norm_w = (const float*)d_in[12];
    float* out = (float*)d_out;

    float *h, *xz, *xc, *xdbl, *dts, *xpp, *opp, *Ps, *Hs;
    __half *xnf,*xcf,*xdf,*yf;
    __half *winf,*woutf,*wxpf,*wdtf,*wembf;
    cudaGetSymbolAddress((void**)&h,    g_h);
    cudaGetSymbolAddress((void**)&xz,   g_xz);
    cudaGetSymbolAddress((void**)&xc,   g_xc);
    cudaGetSymbolAddress((void**)&xdbl, g_xdbl);
    cudaGetSymbolAddress((void**)&dts,  g_dt);
    cudaGetSymbolAddress((void**)&xpp,  g_xpp);
    cudaGetSymbolAddress((void**)&opp,  g_opp);
    cudaGetSymbolAddress((void**)&Ps,   g_Pseg);
    cudaGetSymbolAddress((void**)&Hs,   g_Hseg);
    cudaGetSymbolAddress((void**)&xnf,  g_xn_f);
    cudaGetSymbolAddress((void**)&xcf,  g_xc_f);
    cudaGetSymbolAddress((void**)&xdf,  g_xd_f);
    cudaGetSymbolAddress((void**)&yf,   g_y_f);
    cudaGetSymbolAddress((void**)&winf, g_win_f);
    cudaGetSymbolAddress((void**)&woutf,g_wout_f);
    cudaGetSymbolAddress((void**)&wxpf, g_wxp_f);
    cudaGetSymbolAddress((void**)&wdtf, g_wdt_f);
    cudaGetSymbolAddress((void**)&wembf,g_wemb_f);

    cudaFuncSetAttribute((const void*)mma_gemm<0,128,128,2>, cudaFuncAttributeMaxDynamicSharedMemorySize, SMEMB(128,128));
    cudaFuncSetAttribute((const void*)mma_gemm<2,128,128,2>, cudaFuncAttributeMaxDynamicSharedMemorySize, SMEMB(128,128));

    {
        int n0 = NLAYER*2*DINNER*DMODEL/4;
        int n1 = NLAYER*DMODEL*DINNER/4;
        int n2 = NLAYER*XDBL_W*DINNER/4;
        int n3 = NLAYER*DINNER*DTRANK/4;
        int n4 = VOCAB*DMODEL/4;
        int tot = n0 + n1 + n2 + n3 + n4;
        cvt_all_k<<<(tot+255)/256, 256>>>(in_proj_w, winf, n0,
                                          out_proj_w, woutf, n1,
                                          x_proj_w,  wxpf,  n2,
                                          dt_w,      wdtf,  n3,
                                          embed,     wembf, n4);
    }

    embed_k<<<TTOK, 256>>>(tokens, embed, h);
    rmsnorm_k<<<TTOK, 256>>>(h, norm_w, xnf);   // layer 0 entry norm

    for (int L = 0; L < NLAYER; L++) {
        mma_gemm<0,128,128,2><<<dim3(2*DINNER/128, TTOK/128), 256, SMEMB(128,128)>>>(
            xnf, DMODEL, winf + (size_t)L * 2*DINNER*DMODEL, DMODEL,
            xz, 2*DINNER, nullptr, 2*DINNER, DMODEL, 0);

        conv_silu_k<<<((TTOK/4)*DINNER + 255)/256, 256>>>(
            xz, conv_w + (size_t)L * DINNER*DCONV, conv_b + (size_t)L * DINNER,
            xc, xcf);

        mma_gemm<0,128,128,2><<<dim3(1, TTOK/128, XP_SPLIT), 256, SMEMB(128,128)>>>(
            xcf, DINNER, wxpf + (size_t)L * XDBL_W*DINNER, DINNER,
            xpp, XDBL_W, nullptr, XDBL_W, DINNER/XP_SPLIT, TTOK*XDBL_W);

        reduce_xp_k<<<(TTOK*XDBL_W + 255)/256, 256>>>(xpp, xdbl, xdf);

        mma_gemm<2,128,128,2><<<dim3(DINNER/128, TTOK/128), 256, SMEMB(128,128)>>>(
            xdf, XDBL_W, wdtf + (size_t)L * DINNER*DTRANK, DTRANK,
            dts, DINNER, dt_b + (size_t)L * DINNER, DINNER, DTRANK, 0);

        scan1_k<<<SCBLK, 256>>>(xdbl, dts, xc,
                                A_log + (size_t)L * DINNER*DSTATE, Ps, Hs);
        scan2_k<<<SCBLK, 256>>>(xdbl, dts, xc, xz,
                                A_log + (size_t)L * DINNER*DSTATE,
                                D_skip + (size_t)L * DINNER, Ps, Hs, yf);

        mma_gemm<0,128,128,2><<<dim3(DMODEL/128, TTOK/128, OP_SPLIT), 256, SMEMB(128,128)>>>(
            yf, DINNER, woutf + (size_t)L * DMODEL*DINNER, DINNER,
            opp, DMODEL, nullptr, DMODEL, DINNER/OP_SPLIT, TTOK*DMODEL);

        const float* wn = (L < NLAYER-1) ? (norm_w + (size_t)(L+1) * DMODEL)
                                         : final_norm_w;
        resid_norm_k<<<TTOK, 256>>>(opp, h, wn, xnf);
    }

    mma_gemm<0,128,128,2><<<dim3(VOCAB/128, TTOK/128), 256, SMEMB(128,128)>>>(
        xnf, DMODEL, wembf, DMODEL, out, VOCAB, nullptr, VOCAB, DMODEL, 0);
}